// round 11
// baseline (speedup 1.0000x reference)
#include <cuda_runtime.h>

#define NTHREADS 256
#define GRID_BLOCKS (148 * 16)

// Zero-initialized accumulators; the last block resets them after reading,
// so every graph replay starts from zero.
__device__ double g_iou_sum;
__device__ double g_valid_cnt;
// Completion counter; atomicInc wraps to 0 at gridDim -> self-resetting.
__device__ unsigned int g_count;

// 256-bit read-only global load (sm_100a/sm_103a): two adjacent float4 boxes
// in one LDG.E.256. Densest possible request shape: warp covers 1024B.
__device__ __forceinline__ void ldg_nc_v8(const float4* p, float4& a, float4& b) {
    asm("ld.global.nc.v8.f32 {%0, %1, %2, %3, %4, %5, %6, %7}, [%8];"
        : "=f"(a.x), "=f"(a.y), "=f"(a.z), "=f"(a.w),
          "=f"(b.x), "=f"(b.y), "=f"(b.z), "=f"(b.w)
        : "l"(p));
}

__device__ __forceinline__ void iou_accum(const float4 p, const float4 t,
                                          float& lsum, float& lcnt) {
    float phw = p.z * 0.5f, phh = p.w * 0.5f;
    float thw = t.z * 0.5f, thh = t.w * 0.5f;

    float ix = fminf(p.x + phw, t.x + thw) - fmaxf(p.x - phw, t.x - thw);
    float iy = fminf(p.y + phh, t.y + thh) - fmaxf(p.y - phh, t.y - thh);
    float inter = fmaxf(ix, 0.0f) * fmaxf(iy, 0.0f);

    float area_p = p.z * p.w;          // valid boxes have w,h >= 0
    float area_t = t.z * t.w;
    float iou = inter / (area_p + area_t - inter + 1e-6f);

    bool valid = !(t.z == -1.0f && t.w == -1.0f);  // sentinel [-1]*4
    if (valid) {
        lsum += iou;
        lcnt += 1.0f;
    }
}

__global__ void __launch_bounds__(NTHREADS)
iou_reduce_kernel(const float4* __restrict__ pred,
                  const float4* __restrict__ truth,
                  int n, float* __restrict__ out, int out_size) {
    float lsum = 0.0f;
    float lcnt = 0.0f;

    int idx = blockIdx.x * NTHREADS + threadIdx.x;
    int stride = gridDim.x * NTHREADS;

    int npairs = n >> 1;
    // Natural (non-unrolled) grid-stride loop over box PAIRS:
    // 2 x LDG.E.256 per iteration (MLP_p1=2, the measured-fastest regime),
    // half the load instructions of the float4 version.
    for (int i = idx; i < npairs; i += stride) {
        float4 p0, p1, t0, t1;
        ldg_nc_v8(pred + 2 * i, p0, p1);
        ldg_nc_v8(truth + 2 * i, t0, t1);
        iou_accum(p0, t0, lsum, lcnt);
        iou_accum(p1, t1, lsum, lcnt);
    }
    // Odd-element tail (n is even for this problem; guard for generality).
    if ((n & 1) && idx == 0) {
        float4 p = __ldg(pred + (n - 1));
        float4 t = __ldg(truth + (n - 1));
        iou_accum(p, t, lsum, lcnt);
    }

    // Warp reduce
    #pragma unroll
    for (int off = 16; off > 0; off >>= 1) {
        lsum += __shfl_down_sync(0xffffffffu, lsum, off);
        lcnt += __shfl_down_sync(0xffffffffu, lcnt, off);
    }

    __shared__ float ssum[NTHREADS / 32];
    __shared__ float scnt[NTHREADS / 32];
    int warp = threadIdx.x >> 5;
    int lane = threadIdx.x & 31;
    if (lane == 0) {
        ssum[warp] = lsum;
        scnt[warp] = lcnt;
    }
    __syncthreads();

    __shared__ bool is_last;
    if (threadIdx.x == 0) {
        float bsum = 0.0f, bcnt = 0.0f;
        #pragma unroll
        for (int w = 0; w < NTHREADS / 32; w++) {
            bsum += ssum[w];
            bcnt += scnt[w];
        }
        atomicAdd(&g_iou_sum, (double)bsum);
        atomicAdd(&g_valid_cnt, (double)bcnt);
        __threadfence();
        unsigned int old = atomicInc(&g_count, gridDim.x - 1);
        is_last = (old == gridDim.x - 1);   // wraps to 0 -> self-resetting
    }
    __syncthreads();

    if (is_last && threadIdx.x == 0) {
        double s = g_iou_sum;
        double c = g_valid_cnt;
        float m = (c > 0.0) ? (float)(s / (c < 1.0 ? 1.0 : c)) : 0.0f;
        for (int i = 0; i < out_size; i++) out[i] = m;
        g_iou_sum = 0.0;        // deferred reset for the next replay
        g_valid_cnt = 0.0;
    }
}

extern "C" void kernel_launch(void* const* d_in, const int* in_sizes, int n_in,
                              void* d_out, int out_size) {
    const float4* pred  = (const float4*)d_in[0];
    const float4* truth = (const float4*)d_in[1];
    int n = in_sizes[0] / 4;   // number of boxes (float4 elements)

    int blocks = GRID_BLOCKS;
    int needed = (n / 2 + NTHREADS - 1) / NTHREADS;
    if (blocks > needed) blocks = needed;
    if (blocks < 1) blocks = 1;

    iou_reduce_kernel<<<blocks, NTHREADS>>>(pred, truth, n,
                                            (float*)d_out, out_size);
}

// round 12
// speedup vs baseline: 1.1097x; 1.1097x over previous
#include <cuda_runtime.h>

#define NTHREADS 512
#define GRID_BLOCKS (148 * 8)

// Zero-initialized accumulators; the last block resets them after reading,
// so every graph replay starts from zero.
__device__ double g_iou_sum;
__device__ double g_valid_cnt;
// Completion counter; atomicInc wraps to 0 at gridDim -> self-resetting.
__device__ unsigned int g_count;

// 256-bit read-only global load (sm_103a): two adjacent float4 boxes per LDG.
__device__ __forceinline__ void ldg_nc_v8(const float4* p, float4& a, float4& b) {
    asm("ld.global.nc.v8.f32 {%0, %1, %2, %3, %4, %5, %6, %7}, [%8];"
        : "=f"(a.x), "=f"(a.y), "=f"(a.z), "=f"(a.w),
          "=f"(b.x), "=f"(b.y), "=f"(b.z), "=f"(b.w)
        : "l"(p));
}

__device__ __forceinline__ void iou_accum(const float4 p, const float4 t,
                                          float& lsum, float& lcnt) {
    float phw = p.z * 0.5f, phh = p.w * 0.5f;
    float thw = t.z * 0.5f, thh = t.w * 0.5f;

    float ix = fminf(p.x + phw, t.x + thw) - fmaxf(p.x - phw, t.x - thw);
    float iy = fminf(p.y + phh, t.y + thh) - fmaxf(p.y - phh, t.y - thh);
    float inter = fmaxf(ix, 0.0f) * fmaxf(iy, 0.0f);

    float area_p = p.z * p.w;          // valid boxes have w,h >= 0
    float area_t = t.z * t.w;
    float iou = inter / (area_p + area_t - inter + 1e-6f);

    bool valid = !(t.z == -1.0f && t.w == -1.0f);  // sentinel [-1]*4
    if (valid) {
        lsum += iou;
        lcnt += 1.0f;
    }
}

__global__ void __launch_bounds__(NTHREADS)
iou_reduce_kernel(const float4* __restrict__ pred,
                  const float4* __restrict__ truth,
                  int n, float* __restrict__ out, int out_size) {
    float lsum = 0.0f;
    float lcnt = 0.0f;

    int idx = blockIdx.x * NTHREADS + threadIdx.x;
    int stride = gridDim.x * NTHREADS;

    int npairs = n >> 1;
    // Natural (non-unrolled) grid-stride loop over box pairs:
    // 2 x LDG.E.256 per iteration (MLP_p1=2, the measured-fastest regime).
    for (int i = idx; i < npairs; i += stride) {
        float4 p0, p1, t0, t1;
        ldg_nc_v8(pred + 2 * i, p0, p1);
        ldg_nc_v8(truth + 2 * i, t0, t1);
        iou_accum(p0, t0, lsum, lcnt);
        iou_accum(p1, t1, lsum, lcnt);
    }
    if ((n & 1) && idx == 0) {         // generality guard; n is even here
        float4 p = __ldg(pred + (n - 1));
        float4 t = __ldg(truth + (n - 1));
        iou_accum(p, t, lsum, lcnt);
    }

    // Warp reduce
    #pragma unroll
    for (int off = 16; off > 0; off >>= 1) {
        lsum += __shfl_down_sync(0xffffffffu, lsum, off);
        lcnt += __shfl_down_sync(0xffffffffu, lcnt, off);
    }

    __shared__ float ssum[NTHREADS / 32];
    __shared__ float scnt[NTHREADS / 32];
    int warp = threadIdx.x >> 5;
    int lane = threadIdx.x & 31;
    if (lane == 0) {
        ssum[warp] = lsum;
        scnt[warp] = lcnt;
    }
    __syncthreads();

    __shared__ bool is_last;
    if (threadIdx.x == 0) {
        float bsum = 0.0f, bcnt = 0.0f;
        #pragma unroll
        for (int w = 0; w < NTHREADS / 32; w++) {
            bsum += ssum[w];
            bcnt += scnt[w];
        }
        atomicAdd(&g_iou_sum, (double)bsum);
        atomicAdd(&g_valid_cnt, (double)bcnt);
        __threadfence();
        unsigned int old = atomicInc(&g_count, gridDim.x - 1);
        is_last = (old == gridDim.x - 1);   // wraps to 0 -> self-resetting
    }
    __syncthreads();

    if (is_last && threadIdx.x == 0) {
        double s = g_iou_sum;
        double c = g_valid_cnt;
        float m = (c > 0.0) ? (float)(s / (c < 1.0 ? 1.0 : c)) : 0.0f;
        for (int i = 0; i < out_size; i++) out[i] = m;
        g_iou_sum = 0.0;        // deferred reset for the next replay
        g_valid_cnt = 0.0;
    }
}

extern "C" void kernel_launch(void* const* d_in, const int* in_sizes, int n_in,
                              void* d_out, int out_size) {
    const float4* pred  = (const float4*)d_in[0];
    const float4* truth = (const float4*)d_in[1];
    int n = in_sizes[0] / 4;   // number of boxes (float4 elements)

    int blocks = GRID_BLOCKS;
    int needed = (n / 2 + NTHREADS - 1) / NTHREADS;
    if (blocks > needed) blocks = needed;
    if (blocks < 1) blocks = 1;

    iou_reduce_kernel<<<blocks, NTHREADS>>>(pred, truth, n,
                                            (float*)d_out, out_size);
}